// round 1
// baseline (speedup 1.0000x reference)
#include <cuda_runtime.h>
#include <cuda_bf16.h>
#include <math.h>

// GhostVLAD fused kernel for GB300 (sm_103a).
// Shapes fixed by the problem: N=32, C=512, H=16, W=64 (P=1024), KG=10, VLAD_K=8.
//
// Kernel 1 (grid 16x32, 256 thr, ~166KB dyn smem): per (n, 64-pixel tile):
//   phase A: stream x tile (coalesced) -> smem, simultaneously accumulate
//            logits via packed fma.rn.f32x2 against w (pre-paired in smem)
//   softmax per pixel (all 10 clusters incl. ghosts)
//   phase B: ax[k][c] partial GEMM from the smem x tile (FFMA2, k<8 only)
//   write per-tile partials to device scratch (deterministic, no atomics)
// Kernel 2 (grid 8x32): reduce 16 tile-partials, subtract a_sum*centers,
//   L2-normalize over C, write output (N, 8*512).

#define N_    32
#define C_    512
#define P_    1024
#define KG_   10
#define KV_   8
#define PT_   64          // pixels per CTA tile
#define TILES_ 16         // P_/PT_
#define THREADS_ 256
#define ROW_  513         // padded xs row stride (floats): odd -> conflict-free stores

// smem layout (floats)
#define XS_OFF   0
#define XS_FLT   (PT_ * ROW_)              // 32832
#define WT_OFF   (XS_OFF + XS_FLT)         // 32832
#define WT_FLT   (C_ * KG_)                // 5120 (float2 pairs: [c][kp] kp=0..4)
#define RED_OFF  (WT_OFF + WT_FLT)         // 37952
#define RED_FLT  (4 * PT_ * KG_)           // 2560
#define AS2_OFF  (RED_OFF + RED_FLT)       // 40512
#define AS2_FLT  (PT_ * KV_ * 2)           // 1024 (duplicated pairs [p][k])
#define ASUM_OFF (AS2_OFF + AS2_FLT)       // 41536
#define SMEM_FLT (ASUM_OFF + 16)           // 41552
#define SMEM_BYTES (SMEM_FLT * 4)          // 166208 B

typedef unsigned long long u64_t;

__device__ __forceinline__ u64_t pack2(float lo, float hi) {
    u64_t r; asm("mov.b64 %0, {%1, %2};" : "=l"(r) : "f"(lo), "f"(hi)); return r;
}
__device__ __forceinline__ void unpack2(u64_t v, float& lo, float& hi) {
    asm("mov.b64 {%0, %1}, %2;" : "=f"(lo), "=f"(hi) : "l"(v));
}
__device__ __forceinline__ void fma2(u64_t& d, u64_t a, u64_t b) {
    // d = a * b + d, lanewise on packed f32x2 (Blackwell FFMA2)
    asm("fma.rn.f32x2 %0, %1, %2, %0;" : "+l"(d) : "l"(a), "l"(b));
}

// scratch: per-(n, tile) partial ax[k<8][c] and a_sum[k<8]
__device__ float g_part[N_ * TILES_ * KV_ * C_];   // 8 MiB
__device__ float g_asum[N_ * TILES_ * KV_];

__global__ __launch_bounds__(THREADS_) void ghostvlad_k1(
    const float* __restrict__ x,     // (N, C, P)
    const float* __restrict__ w,     // (KG, C)
    const float* __restrict__ bias)  // (KG,)
{
    extern __shared__ float sm[];
    float*  xs    = sm + XS_OFF;                       // [PT_][ROW_]
    u64_t*  wt2u  = (u64_t*)(sm + WT_OFF);             // [C_][5] packed (w[2kp][c], w[2kp+1][c])
    float2* red2  = (float2*)(sm + RED_OFF);           // [4][PT_][5]
    u64_t*  as2u  = (u64_t*)(sm + AS2_OFF);            // [PT_][KV_] duplicated (a,a)
    float*  asum_s = sm + ASUM_OFF;

    const int tid  = threadIdx.x;
    const int tile = blockIdx.x;
    const int n    = blockIdx.y;
    const int p0   = tile * PT_;

    // phase 0: build paired-transposed weights in smem; zero asum
    for (int i = tid; i < C_ * 5; i += THREADS_) {
        int c = i / 5, kp = i % 5;
        ((float2*)wt2u)[i] = make_float2(w[(2 * kp) * C_ + c], w[(2 * kp + 1) * C_ + c]);
    }
    if (tid < KV_) asum_s[tid] = 0.0f;
    __syncthreads();

    // phase A: load x tile + logits partials
    const int pl = tid & (PT_ - 1);     // pixel lane 0..63
    const int cq = tid >> 6;            // channel quarter 0..3
    const float* xp = x + (size_t)n * C_ * P_ + p0 + pl;

    u64_t lacc[5];
    #pragma unroll
    for (int kp = 0; kp < 5; ++kp) lacc[kp] = pack2(0.0f, 0.0f);

    const int cbase = cq * 128;
    #pragma unroll 4
    for (int i = 0; i < 128; ++i) {
        int c = cbase + i;
        float xv = xp[c * P_];
        xs[pl * ROW_ + c] = xv;
        u64_t xv2 = pack2(xv, xv);
        const u64_t* wr = wt2u + c * 5;
        #pragma unroll
        for (int kp = 0; kp < 5; ++kp) fma2(lacc[kp], xv2, wr[kp]);
    }
    #pragma unroll
    for (int kp = 0; kp < 5; ++kp) {
        float lo, hi; unpack2(lacc[kp], lo, hi);
        red2[(cq * PT_ + pl) * 5 + kp] = make_float2(lo, hi);
    }
    __syncthreads();

    // softmax per pixel (threads 0..63)
    if (tid < PT_) {
        const int p = tid;
        float lg[KG_];
        #pragma unroll
        for (int kp = 0; kp < 5; ++kp) {
            float sx = 0.f, sy = 0.f;
            #pragma unroll
            for (int q = 0; q < 4; ++q) {
                float2 v = red2[(q * PT_ + p) * 5 + kp];
                sx += v.x; sy += v.y;
            }
            lg[2 * kp]     = sx + bias[2 * kp];
            lg[2 * kp + 1] = sy + bias[2 * kp + 1];
        }
        float m = lg[0];
        #pragma unroll
        for (int k = 1; k < KG_; ++k) m = fmaxf(m, lg[k]);
        float e[KG_], s = 0.f;
        #pragma unroll
        for (int k = 0; k < KG_; ++k) { e[k] = __expf(lg[k] - m); s += e[k]; }
        float inv = 1.0f / s;
        #pragma unroll
        for (int k = 0; k < KV_; ++k) {
            float a = e[k] * inv;
            as2u[p * KV_ + k] = pack2(a, a);
            atomicAdd(&asum_s[k], a);
        }
    }
    __syncthreads();

    // phase B: partial ax[k][c] over this tile's 64 pixels (k < 8)
    const int c0 = tid, c1 = tid + 256;
    u64_t acc[KV_];
    #pragma unroll
    for (int k = 0; k < KV_; ++k) acc[k] = pack2(0.0f, 0.0f);

    #pragma unroll 2
    for (int p = 0; p < PT_; ++p) {
        float xa = xs[p * ROW_ + c0];
        float xb = xs[p * ROW_ + c1];
        u64_t xv2 = pack2(xa, xb);
        const u64_t* ap = as2u + p * KV_;
        #pragma unroll
        for (int k = 0; k < KV_; ++k) fma2(acc[k], xv2, ap[k]);
    }

    float* gp = g_part + ((size_t)(n * TILES_ + tile) * KV_) * C_;
    #pragma unroll
    for (int k = 0; k < KV_; ++k) {
        float lo, hi; unpack2(acc[k], lo, hi);
        gp[k * C_ + c0] = lo;
        gp[k * C_ + c1] = hi;
    }
    if (tid < KV_) g_asum[(n * TILES_ + tile) * KV_ + tid] = asum_s[tid];
}

__global__ __launch_bounds__(THREADS_) void ghostvlad_k2(
    const float* __restrict__ centers,  // (KG, C)
    float* __restrict__ out)            // (N, KV_*C)
{
    const int k = blockIdx.x;
    const int n = blockIdx.y;
    const int t = threadIdx.x;

    float s0 = 0.f, s1 = 0.f;
    #pragma unroll
    for (int tile = 0; tile < TILES_; ++tile) {
        const float* pp = g_part + ((size_t)(n * TILES_ + tile) * KV_ + k) * C_;
        s0 += pp[t];
        s1 += pp[t + 256];
    }
    float asum = 0.f;
    #pragma unroll
    for (int tile = 0; tile < TILES_; ++tile)
        asum += g_asum[(n * TILES_ + tile) * KV_ + k];

    float r0 = s0 - asum * centers[k * C_ + t];
    float r1 = s1 - asum * centers[k * C_ + t + 256];

    float ss = r0 * r0 + r1 * r1;
    #pragma unroll
    for (int o = 16; o; o >>= 1) ss += __shfl_xor_sync(0xffffffffu, ss, o);
    __shared__ float ws[8];
    if ((t & 31) == 0) ws[t >> 5] = ss;
    __syncthreads();
    float tot = 0.f;
    #pragma unroll
    for (int i = 0; i < 8; ++i) tot += ws[i];

    float inv = 1.0f / fmaxf(sqrtf(tot), 1e-12f);
    float* op = out + (size_t)n * (KV_ * C_) + k * C_;
    op[t]       = r0 * inv;
    op[t + 256] = r1 * inv;
}

extern "C" void kernel_launch(void* const* d_in, const int* in_sizes, int n_in,
                              void* d_out, int out_size) {
    const float* x       = (const float*)d_in[0];
    const float* conv_w  = (const float*)d_in[1];
    const float* conv_b  = (const float*)d_in[2];
    const float* centers = (const float*)d_in[3];
    float* out = (float*)d_out;

    cudaFuncSetAttribute(ghostvlad_k1,
                         cudaFuncAttributeMaxDynamicSharedMemorySize, SMEM_BYTES);

    dim3 g1(TILES_, N_);
    ghostvlad_k1<<<g1, THREADS_, SMEM_BYTES>>>(x, conv_w, conv_b);

    dim3 g2(KV_, N_);
    ghostvlad_k2<<<g2, THREADS_>>>(centers, out);
}

// round 2
// speedup vs baseline: 2.5365x; 2.5365x over previous
#include <cuda_runtime.h>
#include <cuda_bf16.h>
#include <math.h>

// GhostVLAD — two-pass streaming design for GB300 (sm_103a).
// N=32, C=512, P=1024 (H=16,W=64), KG=10, VLAD_K=8.
//
// kA1: partial logits, c-split 8. grid (8,32) x 256 thr.
// kA2: reduce + softmax + a(n,k,p) + a_sum partials. grid (4,32) x 256 thr.
// kB : ax[n][k][c] = sum_p a*x. grid (16,32) x 256 thr, a staged in smem.
// kC : residual - a_sum*centers, L2 normalize. grid (8,32) x 256 thr.

#define N_   32
#define C_   512
#define P_   1024
#define KG_  10
#define KV_  8
#define CS_  8            // c-split in kA1
#define CCH_ (C_ / CS_)   // 64 channels per kA1 CTA

typedef unsigned long long u64_t;

__device__ __forceinline__ u64_t pack2(float lo, float hi) {
    u64_t r; asm("mov.b64 %0, {%1, %2};" : "=l"(r) : "f"(lo), "f"(hi)); return r;
}
__device__ __forceinline__ void unpack2(u64_t v, float& lo, float& hi) {
    asm("mov.b64 {%0, %1}, %2;" : "=f"(lo), "=f"(hi) : "l"(v));
}
__device__ __forceinline__ void fma2(u64_t& d, u64_t a, u64_t b) {
    asm("fma.rn.f32x2 %0, %1, %2, %0;" : "+l"(d) : "l"(a), "l"(b));
}

// scratch
__device__ float g_part[CS_ * N_ * KG_ * P_];   // 10.5 MiB: [s][n][k][p]
__device__ float g_a[N_ * KV_ * P_];            // 1 MiB:    [n][k][p]
__device__ float g_asum[N_ * 4 * KV_];          // [n][pchunk][k]
__device__ float g_ax[N_ * KV_ * C_];           // [n][k][c]

// ---------------- kA1: partial logits ----------------
__global__ __launch_bounds__(256) void gv_kA1(
    const float* __restrict__ x, const float* __restrict__ w)
{
    __shared__ u64_t wd[CCH_ * KG_];   // (w,w) duplicated, [ci][k]
    const int s = blockIdx.x;
    const int n = blockIdx.y;
    const int t = threadIdx.x;

    for (int i = t; i < CCH_ * KG_; i += 256) {
        int ci = i / KG_, k = i % KG_;
        float wv = w[k * C_ + s * CCH_ + ci];
        wd[i] = pack2(wv, wv);
    }
    __syncthreads();

    const float* xp = x + ((size_t)n * C_ + s * CCH_) * P_ + 4 * t;

    u64_t acc[KG_][2];
    #pragma unroll
    for (int k = 0; k < KG_; ++k) { acc[k][0] = pack2(0.f, 0.f); acc[k][1] = pack2(0.f, 0.f); }

    #pragma unroll 8
    for (int ci = 0; ci < CCH_; ++ci) {
        const float4 xv = *(const float4*)(xp + (size_t)ci * P_);
        u64_t x01 = pack2(xv.x, xv.y);
        u64_t x23 = pack2(xv.z, xv.w);
        const u64_t* wr = wd + ci * KG_;
        #pragma unroll
        for (int k = 0; k < KG_; ++k) {
            fma2(acc[k][0], x01, wr[k]);
            fma2(acc[k][1], x23, wr[k]);
        }
    }

    float* pp = g_part + (((size_t)s * N_ + n) * KG_) * P_ + 4 * t;
    #pragma unroll
    for (int k = 0; k < KG_; ++k) {
        float4 o;
        unpack2(acc[k][0], o.x, o.y);
        unpack2(acc[k][1], o.z, o.w);
        *(float4*)(pp + (size_t)k * P_) = o;
    }
}

// ---------------- kA2: reduce + softmax ----------------
__global__ __launch_bounds__(256) void gv_kA2(const float* __restrict__ bias)
{
    __shared__ float wsum[8][KV_];
    const int pc = blockIdx.x;          // 0..3
    const int n  = blockIdx.y;
    const int t  = threadIdx.x;
    const int p  = pc * 256 + t;
    const int lane = t & 31, wid = t >> 5;

    float lg[KG_];
    #pragma unroll
    for (int k = 0; k < KG_; ++k) {
        float sum = 0.f;
        #pragma unroll
        for (int s = 0; s < CS_; ++s)
            sum += g_part[(((size_t)s * N_ + n) * KG_ + k) * P_ + p];
        lg[k] = sum + bias[k];
    }
    float m = lg[0];
    #pragma unroll
    for (int k = 1; k < KG_; ++k) m = fmaxf(m, lg[k]);
    float e[KG_], ssum = 0.f;
    #pragma unroll
    for (int k = 0; k < KG_; ++k) { e[k] = __expf(lg[k] - m); ssum += e[k]; }
    float inv = 1.0f / ssum;

    float av[KV_];
    #pragma unroll
    for (int k = 0; k < KV_; ++k) {
        av[k] = e[k] * inv;
        g_a[((size_t)n * KV_ + k) * P_ + p] = av[k];
    }
    // deterministic a_sum: warp butterfly then sequential over warps
    #pragma unroll
    for (int k = 0; k < KV_; ++k) {
        float v = av[k];
        #pragma unroll
        for (int o = 16; o; o >>= 1) v += __shfl_xor_sync(0xffffffffu, v, o);
        if (lane == 0) wsum[wid][k] = v;
    }
    __syncthreads();
    if (t < KV_) {
        float v = 0.f;
        #pragma unroll
        for (int wg = 0; wg < 8; ++wg) v += wsum[wg][t];
        g_asum[(n * 4 + pc) * KV_ + t] = v;
    }
}

// ---------------- kB: ax = sum_p a * x ----------------
__global__ __launch_bounds__(256) void gv_kB(const float* __restrict__ x)
{
    __shared__ float a_s[KV_ * P_];     // 32 KB, [k][p]
    const int cc = blockIdx.x;          // 0..15 (32 channels each)
    const int n  = blockIdx.y;
    const int t  = threadIdx.x;
    const int lane = t & 31, wid = t >> 5;

    {
        const float4* ap = (const float4*)(g_a + (size_t)n * KV_ * P_);
        float4* as4 = (float4*)a_s;
        #pragma unroll
        for (int i = 0; i < KV_ * P_ / 4 / 256; ++i)
            as4[t + i * 256] = ap[t + i * 256];
    }
    __syncthreads();

    const int cbase = cc * 32 + wid * 4;
    const float* xb = x + ((size_t)n * C_ + cbase) * P_;

    u64_t acc[4][KV_];
    #pragma unroll
    for (int ch = 0; ch < 4; ++ch)
        #pragma unroll
        for (int k = 0; k < KV_; ++k) acc[ch][k] = pack2(0.f, 0.f);

    #pragma unroll 2
    for (int it = 0; it < 8; ++it) {
        const int p0 = it * 128 + 4 * lane;
        float4 xv[4];
        #pragma unroll
        for (int ch = 0; ch < 4; ++ch)
            xv[ch] = *(const float4*)(xb + (size_t)ch * P_ + p0);
        u64_t a01[KV_], a23[KV_];
        #pragma unroll
        for (int k = 0; k < KV_; ++k) {
            float4 av = *(const float4*)(a_s + k * P_ + p0);
            a01[k] = pack2(av.x, av.y);
            a23[k] = pack2(av.z, av.w);
        }
        #pragma unroll
        for (int ch = 0; ch < 4; ++ch) {
            u64_t x01 = pack2(xv[ch].x, xv[ch].y);
            u64_t x23 = pack2(xv[ch].z, xv[ch].w);
            #pragma unroll
            for (int k = 0; k < KV_; ++k) {
                fma2(acc[ch][k], x01, a01[k]);
                fma2(acc[ch][k], x23, a23[k]);
            }
        }
    }

    // deterministic butterfly over 32 lanes (p-subsets)
    #pragma unroll
    for (int ch = 0; ch < 4; ++ch) {
        #pragma unroll
        for (int k = 0; k < KV_; ++k) {
            float lo, hi; unpack2(acc[ch][k], lo, hi);
            float v = lo + hi;
            #pragma unroll
            for (int o = 16; o; o >>= 1) v += __shfl_xor_sync(0xffffffffu, v, o);
            if (lane == 0)
                g_ax[((size_t)n * KV_ + k) * C_ + cbase + ch] = v;
        }
    }
}

// ---------------- kC: residual + L2 normalize ----------------
__global__ __launch_bounds__(256) void gv_kC(
    const float* __restrict__ centers, float* __restrict__ out)
{
    __shared__ float ws[8];
    const int k = blockIdx.x;
    const int n = blockIdx.y;
    const int t = threadIdx.x;

    float asum = 0.f;
    #pragma unroll
    for (int pc = 0; pc < 4; ++pc) asum += g_asum[(n * 4 + pc) * KV_ + k];

    const float* axp = g_ax + ((size_t)n * KV_ + k) * C_;
    float r0 = axp[t]       - asum * centers[k * C_ + t];
    float r1 = axp[t + 256] - asum * centers[k * C_ + t + 256];

    float ss = r0 * r0 + r1 * r1;
    #pragma unroll
    for (int o = 16; o; o >>= 1) ss += __shfl_xor_sync(0xffffffffu, ss, o);
    if ((t & 31) == 0) ws[t >> 5] = ss;
    __syncthreads();
    float tot = 0.f;
    #pragma unroll
    for (int i = 0; i < 8; ++i) tot += ws[i];

    float inv = 1.0f / fmaxf(sqrtf(tot), 1e-12f);
    float* op = out + (size_t)n * (KV_ * C_) + k * C_;
    op[t]       = r0 * inv;
    op[t + 256] = r1 * inv;
}

extern "C" void kernel_launch(void* const* d_in, const int* in_sizes, int n_in,
                              void* d_out, int out_size) {
    const float* x       = (const float*)d_in[0];
    const float* conv_w  = (const float*)d_in[1];
    const float* conv_b  = (const float*)d_in[2];
    const float* centers = (const float*)d_in[3];
    float* out = (float*)d_out;

    gv_kA1<<<dim3(CS_, N_), 256>>>(x, conv_w);
    gv_kA2<<<dim3(4, N_), 256>>>(conv_b);
    gv_kB <<<dim3(16, N_), 256>>>(x);
    gv_kC <<<dim3(KV_, N_), 256>>>(centers, out);
}

// round 3
// speedup vs baseline: 3.9589x; 1.5608x over previous
#include <cuda_runtime.h>
#include <cuda_bf16.h>
#include <math.h>

// GhostVLAD — 3-kernel streaming design for GB300 (sm_103a).
// N=32, C=512, P=1024, KG=10, VLAD_K=8.
//
// K1: logits + softmax fused. grid (8,32) x 256 thr, 82KB dyn smem.
//     CTA = (128-pixel chunk, n). Emits a[n][k][p] + chunked a_sum.
// K2: ax GEMM + residual + sumsq partials. grid (16,32) x 256 thr.
// K3: normalize residuals. grid (8,32) x 256 thr.

#define N_   32
#define C_   512
#define P_   1024
#define KG_  10
#define KV_  8
#define PCH_ 128                 // pixels per K1 chunk
#define NCH_ (P_ / PCH_)         // 8 chunks

typedef unsigned long long u64_t;

__device__ __forceinline__ u64_t pack2(float lo, float hi) {
    u64_t r; asm("mov.b64 %0, {%1, %2};" : "=l"(r) : "f"(lo), "f"(hi)); return r;
}
__device__ __forceinline__ void unpack2(u64_t v, float& lo, float& hi) {
    asm("mov.b64 {%0, %1}, %2;" : "=f"(lo), "=f"(hi) : "l"(v));
}
__device__ __forceinline__ void fma2(u64_t& d, u64_t a, u64_t b) {
    asm("fma.rn.f32x2 %0, %1, %2, %0;" : "+l"(d) : "l"(a), "l"(b));
}

// scratch
__device__ float g_a[N_ * KV_ * P_];            // [n][k][p]
__device__ float g_asum[N_ * NCH_ * KV_];       // [n][chunk][k]
__device__ float g_r[N_ * KV_ * C_];            // residuals [n][k][c]
__device__ float g_ss[N_ * KV_ * 16];           // sumsq partials [n][k][cc]

// K1 smem layout (bytes)
#define K1_WD_B   (C_ * KG_ * 8)                        // 40960
#define K1_RED_B  (KG_ * 8 * PCH_ * 4)                  // 40960
#define K1_ASB_B  (4 * KV_ * 4)                         // 128
#define K1_SMEM   (K1_WD_B + K1_RED_B + K1_ASB_B)       // 82048

// ---------------- K1: logits + softmax ----------------
__global__ __launch_bounds__(256) void gv_K1(
    const float* __restrict__ x, const float* __restrict__ w,
    const float* __restrict__ bias)
{
    extern __shared__ char smraw[];
    u64_t* wd  = (u64_t*)smraw;                          // [c][k] (w,w)
    float* red = (float*)(smraw + K1_WD_B);              // [k][cs][p]
    float* asb = (float*)(smraw + K1_WD_B + K1_RED_B);   // [wid][k]

    const int pc = blockIdx.x;
    const int n  = blockIdx.y;
    const int t  = threadIdx.x;

    for (int i = t; i < C_ * KG_; i += 256) {
        int c = i / KG_, k = i % KG_;
        float wv = w[k * C_ + c];
        wd[i] = pack2(wv, wv);
    }
    __syncthreads();

    const int cs = t >> 5;          // channel slice 0..7 (64 ch)
    const int pq = t & 31;          // pixel quad 0..31
    const float* xp = x + ((size_t)n * C_ + cs * 64) * P_ + pc * PCH_ + 4 * pq;

    u64_t acc[KG_][2];
    #pragma unroll
    for (int k = 0; k < KG_; ++k) { acc[k][0] = pack2(0.f, 0.f); acc[k][1] = pack2(0.f, 0.f); }

    #pragma unroll 4
    for (int ci = 0; ci < 64; ++ci) {
        const float4 xv = *(const float4*)(xp + (size_t)ci * P_);
        u64_t x01 = pack2(xv.x, xv.y);
        u64_t x23 = pack2(xv.z, xv.w);
        const u64_t* wr = wd + (cs * 64 + ci) * KG_;
        #pragma unroll
        for (int k = 0; k < KG_; ++k) {
            fma2(acc[k][0], x01, wr[k]);
            fma2(acc[k][1], x23, wr[k]);
        }
    }

    #pragma unroll
    for (int k = 0; k < KG_; ++k) {
        float4 o;
        unpack2(acc[k][0], o.x, o.y);
        unpack2(acc[k][1], o.z, o.w);
        *(float4*)(red + (k * 8 + cs) * PCH_ + 4 * pq) = o;   // conflict-free
    }
    __syncthreads();

    if (t < PCH_) {
        const int p = t;
        const int lane = t & 31, wid = t >> 5;
        float lg[KG_];
        #pragma unroll
        for (int k = 0; k < KG_; ++k) {
            float s = 0.f;
            #pragma unroll
            for (int c8 = 0; c8 < 8; ++c8) s += red[(k * 8 + c8) * PCH_ + p];
            lg[k] = s + bias[k];
        }
        float m = lg[0];
        #pragma unroll
        for (int k = 1; k < KG_; ++k) m = fmaxf(m, lg[k]);
        float e[KG_], ssum = 0.f;
        #pragma unroll
        for (int k = 0; k < KG_; ++k) { e[k] = __expf(lg[k] - m); ssum += e[k]; }
        float inv = 1.0f / ssum;

        float av[KV_];
        #pragma unroll
        for (int k = 0; k < KV_; ++k) {
            av[k] = e[k] * inv;
            g_a[((size_t)n * KV_ + k) * P_ + pc * PCH_ + p] = av[k];
        }
        #pragma unroll
        for (int k = 0; k < KV_; ++k) {
            float v = av[k];
            #pragma unroll
            for (int o = 16; o; o >>= 1) v += __shfl_xor_sync(0xffffffffu, v, o);
            if (lane == 0) asb[wid * KV_ + k] = v;
        }
    }
    __syncthreads();
    if (t < KV_) {
        float v = 0.f;
        #pragma unroll
        for (int wg = 0; wg < 4; ++wg) v += asb[wg * KV_ + t];
        g_asum[(n * NCH_ + pc) * KV_ + t] = v;
    }
}

// ---------------- K2: ax GEMM + residual + sumsq partials ----------------
__global__ __launch_bounds__(256) void gv_K2(
    const float* __restrict__ x, const float* __restrict__ centers)
{
    __shared__ float a_s[KV_ * P_];     // 32 KB [k][p]
    __shared__ float asum_s[KV_];
    __shared__ float ssb[8][KV_];

    const int cc = blockIdx.x;          // 0..15 (32 channels)
    const int n  = blockIdx.y;
    const int t  = threadIdx.x;
    const int lane = t & 31, wid = t >> 5;

    {
        const float4* ap = (const float4*)(g_a + (size_t)n * KV_ * P_);
        float4* as4 = (float4*)a_s;
        #pragma unroll
        for (int i = 0; i < KV_ * P_ / 4 / 256; ++i)
            as4[t + i * 256] = ap[t + i * 256];
    }
    if (t < KV_) {
        float v = 0.f;
        #pragma unroll
        for (int pc = 0; pc < NCH_; ++pc) v += g_asum[(n * NCH_ + pc) * KV_ + t];
        asum_s[t] = v;
    }
    __syncthreads();

    const int cbase = cc * 32 + wid * 4;
    const float* xb = x + ((size_t)n * C_ + cbase) * P_;

    u64_t acc[4][KV_];
    #pragma unroll
    for (int ch = 0; ch < 4; ++ch)
        #pragma unroll
        for (int k = 0; k < KV_; ++k) acc[ch][k] = pack2(0.f, 0.f);

    #pragma unroll 2
    for (int it = 0; it < 8; ++it) {
        const int p0 = it * 128 + 4 * lane;
        float4 xv[4];
        #pragma unroll
        for (int ch = 0; ch < 4; ++ch)
            xv[ch] = *(const float4*)(xb + (size_t)ch * P_ + p0);
        u64_t a01[KV_], a23[KV_];
        #pragma unroll
        for (int k = 0; k < KV_; ++k) {
            float4 av = *(const float4*)(a_s + k * P_ + p0);
            a01[k] = pack2(av.x, av.y);
            a23[k] = pack2(av.z, av.w);
        }
        #pragma unroll
        for (int ch = 0; ch < 4; ++ch) {
            u64_t x01 = pack2(xv[ch].x, xv[ch].y);
            u64_t x23 = pack2(xv[ch].z, xv[ch].w);
            #pragma unroll
            for (int k = 0; k < KV_; ++k) {
                fma2(acc[ch][k], x01, a01[k]);
                fma2(acc[ch][k], x23, a23[k]);
            }
        }
    }

    float ssq[KV_];
    #pragma unroll
    for (int k = 0; k < KV_; ++k) ssq[k] = 0.f;

    #pragma unroll
    for (int ch = 0; ch < 4; ++ch) {
        #pragma unroll
        for (int k = 0; k < KV_; ++k) {
            float lo, hi; unpack2(acc[ch][k], lo, hi);
            float v = lo + hi;
            #pragma unroll
            for (int o = 16; o; o >>= 1) v += __shfl_xor_sync(0xffffffffu, v, o);
            if (lane == 0) {
                const int c = cbase + ch;
                float r = v - asum_s[k] * centers[k * C_ + c];
                g_r[((size_t)n * KV_ + k) * C_ + c] = r;
                ssq[k] += r * r;
            }
        }
    }
    if (lane == 0) {
        #pragma unroll
        for (int k = 0; k < KV_; ++k) ssb[wid][k] = ssq[k];
    }
    __syncthreads();
    if (t < KV_) {
        float v = 0.f;
        #pragma unroll
        for (int wg = 0; wg < 8; ++wg) v += ssb[wg][t];
        g_ss[((size_t)n * KV_ + t) * 16 + cc] = v;
    }
}

// ---------------- K3: normalize ----------------
__global__ __launch_bounds__(256) void gv_K3(float* __restrict__ out)
{
    const int k = blockIdx.x;
    const int n = blockIdx.y;
    const int t = threadIdx.x;

    float ss = 0.f;
    #pragma unroll
    for (int cc = 0; cc < 16; ++cc) ss += g_ss[((size_t)n * KV_ + k) * 16 + cc];
    float inv = 1.0f / fmaxf(sqrtf(ss), 1e-12f);

    const float* rp = g_r + ((size_t)n * KV_ + k) * C_;
    float* op = out + (size_t)n * (KV_ * C_) + k * C_;
    op[t]       = rp[t]       * inv;
    op[t + 256] = rp[t + 256] * inv;
}

extern "C" void kernel_launch(void* const* d_in, const int* in_sizes, int n_in,
                              void* d_out, int out_size) {
    const float* x       = (const float*)d_in[0];
    const float* conv_w  = (const float*)d_in[1];
    const float* conv_b  = (const float*)d_in[2];
    const float* centers = (const float*)d_in[3];
    float* out = (float*)d_out;

    cudaFuncSetAttribute(gv_K1,
                         cudaFuncAttributeMaxDynamicSharedMemorySize, K1_SMEM);

    gv_K1<<<dim3(NCH_, N_), 256, K1_SMEM>>>(x, conv_w, conv_b);
    gv_K2<<<dim3(16, N_), 256>>>(x, centers);
    gv_K3<<<dim3(KV_, N_), 256>>>(out);
}